// round 13
// baseline (speedup 1.0000x reference)
#include <cuda_runtime.h>

#define NB     16
#define CDIM   256
#define NHEADS 4
#define CHD    64
#define CKD    16
#define CD     64
#define CRES   40
#define NPIX   1600
#define EPSB   1e-5f
#define LOG2E  1.4426950408889634f

// ---------------- scratch (device globals; no allocation allowed) ----------
__device__ float g_xi[NB * CHD * NPIX];    // per-head conv output
__device__ float g_q [NB * CKD * NPIX];
__device__ float g_k [NB * CKD * NPIX];
__device__ float g_v [NB * CD  * NPIX];
__device__ float g_o [NB * CDIM * NPIX];   // concatenated head outputs

// Fast exp2 for t <= 0 (FMA pipe, avoids MUFU throughput wall).
// |rel err| ~3e-6 on f in [-0.5, 0.5].
__device__ __forceinline__ float fexp2(float t) {
    t = fmaxf(t, -126.0f);
    float z = t + 12582912.0f;                 // round-to-nearest via magic const
    int   e = __float_as_int(z) - 0x4B400000;  // integer part (signed)
    float f = t - (z - 12582912.0f);           // f in [-0.5, 0.5]
    float p = 1.3333558146e-3f;
    p = fmaf(p, f, 9.6181291076e-3f);
    p = fmaf(p, f, 5.5504108664e-2f);
    p = fmaf(p, f, 2.4022650696e-1f);
    p = fmaf(p, f, 6.9314718056e-1f);
    p = fmaf(p, f, 1.0f);                      // 2^f
    return __int_as_float(__float_as_int(p) + (e << 23));
}

// ---------------- depthwise 5x5 conv + BN (+ cascade add) ------------------
__global__ __launch_bounds__(256) void dwconv_kernel(
    const float* __restrict__ x, const float* __restrict__ dw_w,
    const float* __restrict__ dg, const float* __restrict__ db,
    const float* __restrict__ dm, const float* __restrict__ dv, int head)
{
    __shared__ float tile[44 * 44];
    __shared__ float wsh[25];
    __shared__ float sc_s, bi_s;
    int c = blockIdx.x, b = blockIdx.y;
    int tid = threadIdx.x;

    const float* xin = x + ((size_t)b * CDIM + head * CHD + c) * NPIX;
    for (int e = tid; e < 44 * 44; e += 256) {
        int yy = e / 44 - 2, xx = e % 44 - 2;
        float v = 0.f;
        if (yy >= 0 && yy < CRES && xx >= 0 && xx < CRES) v = xin[yy * CRES + xx];
        tile[e] = v;
    }
    if (tid < 25) wsh[tid] = dw_w[((size_t)head * CHD + c) * 25 + tid];
    if (tid == 0) {
        int idx = head * CHD + c;
        float s = dg[idx] * rsqrtf(dv[idx] + EPSB);
        sc_s = s; bi_s = db[idx] - dm[idx] * s;
    }
    __syncthreads();

    float* outp = g_xi + ((size_t)b * CHD + c) * NPIX;
    const float* prevp = g_o + ((size_t)b * CDIM + (head - 1) * CHD + c) * NPIX;
    float s = sc_s, bi = bi_s;
    for (int p = tid; p < NPIX; p += 256) {
        int py = p / CRES, px = p % CRES;
        float a = 0.f;
#pragma unroll
        for (int ky = 0; ky < 5; ky++)
#pragma unroll
            for (int kx = 0; kx < 5; kx++)
                a = fmaf(tile[(py + ky) * 44 + px + kx], wsh[ky * 5 + kx], a);
        a = fmaf(a, s, bi);
        if (head > 0) a += prevp[p];
        outp[p] = a;
    }
}

// ---------------- fused QKV 96x64 GEMM with BN folded ----------------------
__global__ __launch_bounds__(128) void qkv_kernel(
    const float* __restrict__ q_w, const float* __restrict__ q_g,
    const float* __restrict__ q_b, const float* __restrict__ q_m,
    const float* __restrict__ q_v,
    const float* __restrict__ k_w, const float* __restrict__ k_g,
    const float* __restrict__ k_b, const float* __restrict__ k_m,
    const float* __restrict__ k_v,
    const float* __restrict__ v_w, const float* __restrict__ v_g,
    const float* __restrict__ v_b, const float* __restrict__ v_m,
    const float* __restrict__ v_v, int head)
{
    __shared__ float Ws[64 * 97];   // [c][row 0..95] (BN scale folded)
    __shared__ float Xs[64 * 64];   // [c][n]
    __shared__ float s_arr[96], t_arr[96];

    int nt = blockIdx.x, b = blockIdx.y;
    int n0 = nt * 64;
    int tid = threadIdx.x;
    int ty = tid >> 3, tx = tid & 7;

    if (tid < 96) {
        float g, bb, m, vv;
        if (tid < 16)      { int r = tid;      g = q_g[head*CKD+r]; bb = q_b[head*CKD+r]; m = q_m[head*CKD+r]; vv = q_v[head*CKD+r]; }
        else if (tid < 32) { int r = tid - 16; g = k_g[head*CKD+r]; bb = k_b[head*CKD+r]; m = k_m[head*CKD+r]; vv = k_v[head*CKD+r]; }
        else               { int r = tid - 32; g = v_g[head*CD +r]; bb = v_b[head*CD +r]; m = v_m[head*CD +r]; vv = v_v[head*CD +r]; }
        float sc = g * rsqrtf(vv + EPSB);
        s_arr[tid] = sc; t_arr[tid] = bb - m * sc;
    }
    __syncthreads();

    for (int e = tid; e < 96 * 64; e += 128) {
        int c = e & 63, r = e >> 6;
        const float* wsrc;
        if (r < 16)      wsrc = q_w + ((size_t)head * CKD + r) * CHD;
        else if (r < 32) wsrc = k_w + ((size_t)head * CKD + (r - 16)) * CHD;
        else             wsrc = v_w + ((size_t)head * CD  + (r - 32)) * CHD;
        Ws[c * 97 + r] = wsrc[c] * s_arr[r];
    }
    for (int e = tid; e < 64 * 64; e += 128) {
        int n = e & 63, c = e >> 6;
        Xs[c * 64 + n] = g_xi[((size_t)b * CHD + c) * NPIX + n0 + n];
    }
    __syncthreads();

    float acc[6][8];
#pragma unroll
    for (int r = 0; r < 6; r++)
#pragma unroll
        for (int c = 0; c < 8; c++) acc[r][c] = 0.f;

#pragma unroll 4
    for (int c = 0; c < 64; c++) {
        float4 x0 = *(const float4*)&Xs[c * 64 + tx * 8];
        float4 x1 = *(const float4*)&Xs[c * 64 + tx * 8 + 4];
#pragma unroll
        for (int rr = 0; rr < 6; rr++) {
            float w = Ws[c * 97 + ty * 6 + rr];
            acc[rr][0] = fmaf(w, x0.x, acc[rr][0]);
            acc[rr][1] = fmaf(w, x0.y, acc[rr][1]);
            acc[rr][2] = fmaf(w, x0.z, acc[rr][2]);
            acc[rr][3] = fmaf(w, x0.w, acc[rr][3]);
            acc[rr][4] = fmaf(w, x1.x, acc[rr][4]);
            acc[rr][5] = fmaf(w, x1.y, acc[rr][5]);
            acc[rr][6] = fmaf(w, x1.z, acc[rr][6]);
            acc[rr][7] = fmaf(w, x1.w, acc[rr][7]);
        }
    }

#pragma unroll
    for (int rr = 0; rr < 6; rr++) {
        int r = ty * 6 + rr;
        float tv = t_arr[r];
        float* dst;
        if (r < 16)      dst = g_q + ((size_t)b * CKD + r) * NPIX + n0;
        else if (r < 32) dst = g_k + ((size_t)b * CKD + (r - 16)) * NPIX + n0;
        else             dst = g_v + ((size_t)b * CD  + (r - 32)) * NPIX + n0;
        float4 o0, o1;
        o0.x = acc[rr][0] + tv; o0.y = acc[rr][1] + tv;
        o0.z = acc[rr][2] + tv; o0.w = acc[rr][3] + tv;
        o1.x = acc[rr][4] + tv; o1.y = acc[rr][5] + tv;
        o1.z = acc[rr][6] + tv; o1.w = acc[rr][7] + tv;
        *(float4*)&dst[tx * 8]     = o0;
        *(float4*)&dst[tx * 8 + 4] = o1;
    }
}

// ---------------- flash-style attention, 64q x 64k tiles, 256 threads ------
// Thread layout: ty = tid>>4 (0..15) -> 4 query rows; tx = tid&15 -> 4 key cols.
__global__ __launch_bounds__(256) void attn_kernel(
    const float* __restrict__ attn_bias, int head)
{
    __shared__ float Qs[CKD * 64];
    __shared__ float Ks[CKD * 64];
    __shared__ float Vt[64 * 68];   // [m][d], padded; reused for output transpose
    __shared__ float Ps[64 * 68];   // [q][m], padded for float4 alignment
    __shared__ float Bs[64];

    int qt = blockIdx.x, b = blockIdx.y;
    int tid = threadIdx.x;
    int ty = tid >> 4, tx = tid & 15;

    const float* qp = g_q + ((size_t)b * CKD) * NPIX + qt * 64;
    const float* kp = g_k + ((size_t)b * CKD) * NPIX;
    const float* vp = g_v + ((size_t)b * CD ) * NPIX;
    const float* bp = attn_bias + (size_t)head * NPIX;

    for (int e = tid; e < CKD * 64; e += 256) {
        int kd = e >> 6, r = e & 63;
        Qs[kd * 64 + r] = qp[(size_t)kd * NPIX + r];
    }

    float acc[4][4];
    float mrun[4], lrun[4];
#pragma unroll
    for (int r = 0; r < 4; r++) {
        mrun[r] = -1e30f; lrun[r] = 0.f;
#pragma unroll
        for (int c = 0; c < 4; c++) acc[r][c] = 0.f;
    }
    const float CLOG = 0.25f * LOG2E;   // SCALE * log2(e)

    for (int kt = 0; kt < 25; kt++) {
        __syncthreads();
        {
            const float* kpt = kp + kt * 64;
            for (int e = tid; e < CKD * 64; e += 256) {
                int kd = e >> 6, c = e & 63;
                Ks[kd * 64 + c] = kpt[(size_t)kd * NPIX + c];
            }
            const float* vpt = vp + kt * 64;
            for (int e = tid; e < CD * 64; e += 256) {
                int dd = e >> 6, m = e & 63;
                Vt[m * 68 + dd] = vpt[(size_t)dd * NPIX + m];
            }
            if (tid < 64) Bs[tid] = bp[kt * 64 + tid] * LOG2E;
        }
        __syncthreads();

        float s[4][4];
#pragma unroll
        for (int r = 0; r < 4; r++)
#pragma unroll
            for (int c = 0; c < 4; c++) s[r][c] = 0.f;

        // QK^T: per kd, one LDS.128 for K frag + one LDS.128 for Q frag
#pragma unroll
        for (int kd = 0; kd < CKD; kd++) {
            float4 kv = *(const float4*)&Ks[kd * 64 + tx * 4];
            float4 qv = *(const float4*)&Qs[kd * 64 + ty * 4];
            s[0][0] = fmaf(qv.x, kv.x, s[0][0]);
            s[0][1] = fmaf(qv.x, kv.y, s[0][1]);
            s[0][2] = fmaf(qv.x, kv.z, s[0][2]);
            s[0][3] = fmaf(qv.x, kv.w, s[0][3]);
            s[1][0] = fmaf(qv.y, kv.x, s[1][0]);
            s[1][1] = fmaf(qv.y, kv.y, s[1][1]);
            s[1][2] = fmaf(qv.y, kv.z, s[1][2]);
            s[1][3] = fmaf(qv.y, kv.w, s[1][3]);
            s[2][0] = fmaf(qv.z, kv.x, s[2][0]);
            s[2][1] = fmaf(qv.z, kv.y, s[2][1]);
            s[2][2] = fmaf(qv.z, kv.z, s[2][2]);
            s[2][3] = fmaf(qv.z, kv.w, s[2][3]);
            s[3][0] = fmaf(qv.w, kv.x, s[3][0]);
            s[3][1] = fmaf(qv.w, kv.y, s[3][1]);
            s[3][2] = fmaf(qv.w, kv.z, s[3][2]);
            s[3][3] = fmaf(qv.w, kv.w, s[3][3]);
        }

        float b0 = Bs[tx * 4], b1 = Bs[tx * 4 + 1], b2 = Bs[tx * 4 + 2], b3 = Bs[tx * 4 + 3];
#pragma unroll
        for (int r = 0; r < 4; r++) {
            s[r][0] = fmaf(s[r][0], CLOG, b0);
            s[r][1] = fmaf(s[r][1], CLOG, b1);
            s[r][2] = fmaf(s[r][2], CLOG, b2);
            s[r][3] = fmaf(s[r][3], CLOG, b3);

            float mx = fmaxf(fmaxf(s[r][0], s[r][1]), fmaxf(s[r][2], s[r][3]));
            mx = fmaxf(mx, __shfl_xor_sync(0xffffffffu, mx, 1));
            mx = fmaxf(mx, __shfl_xor_sync(0xffffffffu, mx, 2));
            mx = fmaxf(mx, __shfl_xor_sync(0xffffffffu, mx, 4));
            mx = fmaxf(mx, __shfl_xor_sync(0xffffffffu, mx, 8));
            float mn  = fmaxf(mrun[r], mx);
            float fac = fexp2(mrun[r] - mn);
            mrun[r] = mn;

            float p0 = fexp2(s[r][0] - mn);
            float p1 = fexp2(s[r][1] - mn);
            float p2 = fexp2(s[r][2] - mn);
            float p3 = fexp2(s[r][3] - mn);
            float4 pq; pq.x = p0; pq.y = p1; pq.z = p2; pq.w = p3;
            *(float4*)&Ps[(ty * 4 + r) * 68 + tx * 4] = pq;
            float rs = (p0 + p1) + (p2 + p3);
            rs += __shfl_xor_sync(0xffffffffu, rs, 1);
            rs += __shfl_xor_sync(0xffffffffu, rs, 2);
            rs += __shfl_xor_sync(0xffffffffu, rs, 4);
            rs += __shfl_xor_sync(0xffffffffu, rs, 8);
            lrun[r] = lrun[r] * fac + rs;
            acc[r][0] *= fac; acc[r][1] *= fac;
            acc[r][2] *= fac; acc[r][3] *= fac;
        }
        __syncthreads();

        // P·V: m blocked by 4; Ps rows loaded as float4.
#pragma unroll 2
        for (int m0 = 0; m0 < 64; m0 += 4) {
            float4 p0v = *(const float4*)&Ps[(ty * 4 + 0) * 68 + m0];
            float4 p1v = *(const float4*)&Ps[(ty * 4 + 1) * 68 + m0];
            float4 p2v = *(const float4*)&Ps[(ty * 4 + 2) * 68 + m0];
            float4 p3v = *(const float4*)&Ps[(ty * 4 + 3) * 68 + m0];
            float4 v0 = *(const float4*)&Vt[(m0 + 0) * 68 + tx * 4];
            float4 v1 = *(const float4*)&Vt[(m0 + 1) * 68 + tx * 4];
            float4 v2 = *(const float4*)&Vt[(m0 + 2) * 68 + tx * 4];
            float4 v3 = *(const float4*)&Vt[(m0 + 3) * 68 + tx * 4];

#define PV_STEP(PR, ROW)                                      \
            acc[ROW][0] = fmaf(PR.x, v0.x, acc[ROW][0]);      \
            acc[ROW][1] = fmaf(PR.x, v0.y, acc[ROW][1]);      \
            acc[ROW][2] = fmaf(PR.x, v0.z, acc[ROW][2]);      \
            acc[ROW][3] = fmaf(PR.x, v0.w, acc[ROW][3]);      \
            acc[ROW][0] = fmaf(PR.y, v1.x, acc[ROW][0]);      \
            acc[ROW][1] = fmaf(PR.y, v1.y, acc[ROW][1]);      \
            acc[ROW][2] = fmaf(PR.y, v1.z, acc[ROW][2]);      \
            acc[ROW][3] = fmaf(PR.y, v1.w, acc[ROW][3]);      \
            acc[ROW][0] = fmaf(PR.z, v2.x, acc[ROW][0]);      \
            acc[ROW][1] = fmaf(PR.z, v2.y, acc[ROW][1]);      \
            acc[ROW][2] = fmaf(PR.z, v2.z, acc[ROW][2]);      \
            acc[ROW][3] = fmaf(PR.z, v2.w, acc[ROW][3]);      \
            acc[ROW][0] = fmaf(PR.w, v3.x, acc[ROW][0]);      \
            acc[ROW][1] = fmaf(PR.w, v3.y, acc[ROW][1]);      \
            acc[ROW][2] = fmaf(PR.w, v3.z, acc[ROW][2]);      \
            acc[ROW][3] = fmaf(PR.w, v3.w, acc[ROW][3]);

            PV_STEP(p0v, 0)
            PV_STEP(p1v, 1)
            PV_STEP(p2v, 2)
            PV_STEP(p3v, 3)
#undef PV_STEP
        }
    }

    __syncthreads();
    // stage transpose [d][q] into Vt for coalesced global write
#pragma unroll
    for (int r = 0; r < 4; r++) {
        float inv = 1.0f / lrun[r];
#pragma unroll
        for (int c = 0; c < 4; c++)
            Vt[(tx * 4 + c) * 68 + ty * 4 + r] = acc[r][c] * inv;
    }
    __syncthreads();
    float* op = g_o + ((size_t)b * CDIM + head * CD) * NPIX + qt * 64;
    for (int e = tid; e < CD * 64; e += 256) {
        int dd = e >> 6, r = e & 63;
        op[(size_t)dd * NPIX + r] = Vt[dd * 68 + r];
    }
}

// ---------------- final 256x256 projection + BN + ReLU ---------------------
__global__ __launch_bounds__(128) void proj_kernel(
    const float* __restrict__ proj_w, const float* __restrict__ pg,
    const float* __restrict__ pb, const float* __restrict__ pm,
    const float* __restrict__ pv, float* __restrict__ out)
{
    __shared__ float Ws[64 * 65];   // [c][o]
    __shared__ float Xs[64 * 64];   // [c][n]

    int nt = blockIdx.x, ot = blockIdx.y, b = blockIdx.z;
    int tid = threadIdx.x;
    int ty = tid >> 4, tx = tid & 15;
    int n0 = nt * 64, o0 = ot * 64;

    float acc[8][4];
#pragma unroll
    for (int r = 0; r < 8; r++)
#pragma unroll
        for (int c = 0; c < 4; c++) acc[r][c] = 0.f;

    for (int ck = 0; ck < 4; ck++) {
        __syncthreads();
        for (int e = tid; e < 4096; e += 128) {
            int c = e & 63, o = e >> 6;
            Ws[c * 65 + o] = proj_w[(size_t)(o0 + o) * CDIM + ck * 64 + c];
        }
        for (int e = tid; e < 4096; e += 128) {
            int n = e & 63, c = e >> 6;
            Xs[c * 64 + n] = g_o[((size_t)b * CDIM + ck * 64 + c) * NPIX + n0 + n];
        }
        __syncthreads();
#pragma unroll 4
        for (int c = 0; c < 64; c++) {
            float4 xv = *(const float4*)&Xs[c * 64 + tx * 4];
#pragma unroll
            for (int r = 0; r < 8; r++) {
                float wv = Ws[c * 65 + ty * 8 + r];
                acc[r][0] = fmaf(wv, xv.x, acc[r][0]);
                acc[r][1] = fmaf(wv, xv.y, acc[r][1]);
                acc[r][2] = fmaf(wv, xv.z, acc[r][2]);
                acc[r][3] = fmaf(wv, xv.w, acc[r][3]);
            }
        }
    }

#pragma unroll
    for (int r = 0; r < 8; r++) {
        int o = o0 + ty * 8 + r;
        float sc = pg[o] * rsqrtf(pv[o] + EPSB);
        float tv = pb[o] - pm[o] * sc;
        float4 res;
        res.x = fmaxf(fmaf(acc[r][0], sc, tv), 0.f);
        res.y = fmaxf(fmaf(acc[r][1], sc, tv), 0.f);
        res.z = fmaxf(fmaf(acc[r][2], sc, tv), 0.f);
        res.w = fmaxf(fmaf(acc[r][3], sc, tv), 0.f);
        *(float4*)&out[((size_t)b * CDIM + o) * NPIX + n0 + tx * 4] = res;
    }
}

// ---------------------------------------------------------------------------
extern "C" void kernel_launch(void* const* d_in, const int* in_sizes, int n_in,
                              void* d_out, int out_size)
{
    (void)in_sizes; (void)n_in; (void)out_size;
    const float* x      = (const float*)d_in[0];
    const float* dw_w   = (const float*)d_in[1];
    const float* dw_g   = (const float*)d_in[2];
    const float* dw_b   = (const float*)d_in[3];
    const float* dw_m   = (const float*)d_in[4];
    const float* dw_v   = (const float*)d_in[5];
    const float* q_w    = (const float*)d_in[6];
    const float* q_g    = (const float*)d_in[7];
    const float* q_b    = (const float*)d_in[8];
    const float* q_m    = (const float*)d_in[9];
    const float* q_v    = (const float*)d_in[10];
    const float* k_w    = (const float*)d_in[11];
    const float* k_g    = (const float*)d_in[12];
    const float* k_b    = (const float*)d_in[13];
    const float* k_m    = (const float*)d_in[14];
    const float* k_v    = (const float*)d_in[15];
    const float* v_w    = (const float*)d_in[16];
    const float* v_g    = (const float*)d_in[17];
    const float* v_b    = (const float*)d_in[18];
    const float* v_m    = (const float*)d_in[19];
    const float* v_v    = (const float*)d_in[20];
    const float* proj_w = (const float*)d_in[21];
    const float* proj_g = (const float*)d_in[22];
    const float* proj_b = (const float*)d_in[23];
    const float* proj_m = (const float*)d_in[24];
    const float* proj_v = (const float*)d_in[25];
    const float* abias  = (const float*)d_in[26];
    float* out = (float*)d_out;

    for (int h = 0; h < NHEADS; h++) {
        dwconv_kernel<<<dim3(CHD, NB), 256>>>(x, dw_w, dw_g, dw_b, dw_m, dw_v, h);
        qkv_kernel<<<dim3(25, NB), 128>>>(q_w, q_g, q_b, q_m, q_v,
                                          k_w, k_g, k_b, k_m, k_v,
                                          v_w, v_g, v_b, v_m, v_v, h);
        attn_kernel<<<dim3(25, NB), 256>>>(abias, h);
    }
    proj_kernel<<<dim3(25, 4, NB), 128>>>(proj_w, proj_g, proj_b, proj_m, proj_v, out);
}

// round 16
// speedup vs baseline: 1.2209x; 1.2209x over previous
#include <cuda_runtime.h>
#include <cstdint>

#define NB     16
#define CDIM   256
#define NHEADS 4
#define CHD    64
#define CKD    16
#define CD     64
#define CRES   40
#define NPIX   1600
#define EPSB   1e-5f
#define LOG2E  1.4426950408889634f

// ---------------- scratch (device globals; no allocation allowed) ----------
__device__ float g_xi[NB * CHD * NPIX];    // per-head conv output
__device__ float g_q [NB * CKD * NPIX];
__device__ float g_k [NB * CKD * NPIX];
__device__ float g_v [NB * CD  * NPIX];
__device__ float g_o [NB * CDIM * NPIX];   // concatenated head outputs

// Fast exp2 for t <= 0 (FMA pipe, avoids MUFU throughput wall).
__device__ __forceinline__ float fexp2(float t) {
    t = fmaxf(t, -126.0f);
    float z = t + 12582912.0f;
    int   e = __float_as_int(z) - 0x4B400000;
    float f = t - (z - 12582912.0f);
    float p = 1.3333558146e-3f;
    p = fmaf(p, f, 9.6181291076e-3f);
    p = fmaf(p, f, 5.5504108664e-2f);
    p = fmaf(p, f, 2.4022650696e-1f);
    p = fmaf(p, f, 6.9314718056e-1f);
    p = fmaf(p, f, 1.0f);
    return __int_as_float(__float_as_int(p) + (e << 23));
}

__device__ __forceinline__ uint32_t f2tf32(float v) {
    uint32_t t;
    asm("cvt.rna.tf32.f32 %0, %1;" : "=r"(t) : "f"(v));
    return t;
}

__device__ __forceinline__ void mma_tf32(
    float& c0, float& c1, float& c2, float& c3,
    uint32_t a0, uint32_t a1, uint32_t a2, uint32_t a3,
    uint32_t b0, uint32_t b1)
{
    asm volatile(
        "mma.sync.aligned.m16n8k8.row.col.f32.tf32.tf32.f32 "
        "{%0,%1,%2,%3}, {%4,%5,%6,%7}, {%8,%9}, {%0,%1,%2,%3};"
        : "+f"(c0), "+f"(c1), "+f"(c2), "+f"(c3)
        : "r"(a0), "r"(a1), "r"(a2), "r"(a3), "r"(b0), "r"(b1));
}

// ---------------- depthwise 5x5 conv + BN (+ cascade add) ------------------
__global__ __launch_bounds__(256) void dwconv_kernel(
    const float* __restrict__ x, const float* __restrict__ dw_w,
    const float* __restrict__ dg, const float* __restrict__ db,
    const float* __restrict__ dm, const float* __restrict__ dv, int head)
{
    __shared__ float tile[44 * 44];
    __shared__ float wsh[25];
    __shared__ float sc_s, bi_s;
    int c = blockIdx.x, b = blockIdx.y;
    int tid = threadIdx.x;

    const float* xin = x + ((size_t)b * CDIM + head * CHD + c) * NPIX;
    for (int e = tid; e < 44 * 44; e += 256) {
        int yy = e / 44 - 2, xx = e % 44 - 2;
        float v = 0.f;
        if (yy >= 0 && yy < CRES && xx >= 0 && xx < CRES) v = xin[yy * CRES + xx];
        tile[e] = v;
    }
    if (tid < 25) wsh[tid] = dw_w[((size_t)head * CHD + c) * 25 + tid];
    if (tid == 0) {
        int idx = head * CHD + c;
        float s = dg[idx] * rsqrtf(dv[idx] + EPSB);
        sc_s = s; bi_s = db[idx] - dm[idx] * s;
    }
    __syncthreads();

    float* outp = g_xi + ((size_t)b * CHD + c) * NPIX;
    const float* prevp = g_o + ((size_t)b * CDIM + (head - 1) * CHD + c) * NPIX;
    float s = sc_s, bi = bi_s;
    for (int p = tid; p < NPIX; p += 256) {
        int py = p / CRES, px = p % CRES;
        float a = 0.f;
#pragma unroll
        for (int ky = 0; ky < 5; ky++)
#pragma unroll
            for (int kx = 0; kx < 5; kx++)
                a = fmaf(tile[(py + ky) * 44 + px + kx], wsh[ky * 5 + kx], a);
        a = fmaf(a, s, bi);
        if (head > 0) a += prevp[p];
        outp[p] = a;
    }
}

// ---------------- fused QKV 96x64 GEMM with BN folded ----------------------
__global__ __launch_bounds__(128) void qkv_kernel(
    const float* __restrict__ q_w, const float* __restrict__ q_g,
    const float* __restrict__ q_b, const float* __restrict__ q_m,
    const float* __restrict__ q_v,
    const float* __restrict__ k_w, const float* __restrict__ k_g,
    const float* __restrict__ k_b, const float* __restrict__ k_m,
    const float* __restrict__ k_v,
    const float* __restrict__ v_w, const float* __restrict__ v_g,
    const float* __restrict__ v_b, const float* __restrict__ v_m,
    const float* __restrict__ v_v, int head)
{
    __shared__ float Ws[64 * 97];
    __shared__ float Xs[64 * 64];
    __shared__ float s_arr[96], t_arr[96];

    int nt = blockIdx.x, b = blockIdx.y;
    int n0 = nt * 64;
    int tid = threadIdx.x;
    int ty = tid >> 3, tx = tid & 7;

    if (tid < 96) {
        float g, bb, m, vv;
        if (tid < 16)      { int r = tid;      g = q_g[head*CKD+r]; bb = q_b[head*CKD+r]; m = q_m[head*CKD+r]; vv = q_v[head*CKD+r]; }
        else if (tid < 32) { int r = tid - 16; g = k_g[head*CKD+r]; bb = k_b[head*CKD+r]; m = k_m[head*CKD+r]; vv = k_v[head*CKD+r]; }
        else               { int r = tid - 32; g = v_g[head*CD +r]; bb = v_b[head*CD +r]; m = v_m[head*CD +r]; vv = v_v[head*CD +r]; }
        float sc = g * rsqrtf(vv + EPSB);
        s_arr[tid] = sc; t_arr[tid] = bb - m * sc;
    }
    __syncthreads();

    for (int e = tid; e < 96 * 64; e += 128) {
        int c = e & 63, r = e >> 6;
        const float* wsrc;
        if (r < 16)      wsrc = q_w + ((size_t)head * CKD + r) * CHD;
        else if (r < 32) wsrc = k_w + ((size_t)head * CKD + (r - 16)) * CHD;
        else             wsrc = v_w + ((size_t)head * CD  + (r - 32)) * CHD;
        Ws[c * 97 + r] = wsrc[c] * s_arr[r];
    }
    for (int e = tid; e < 64 * 64; e += 128) {
        int n = e & 63, c = e >> 6;
        Xs[c * 64 + n] = g_xi[((size_t)b * CHD + c) * NPIX + n0 + n];
    }
    __syncthreads();

    float acc[6][8];
#pragma unroll
    for (int r = 0; r < 6; r++)
#pragma unroll
        for (int c = 0; c < 8; c++) acc[r][c] = 0.f;

#pragma unroll 4
    for (int c = 0; c < 64; c++) {
        float4 x0 = *(const float4*)&Xs[c * 64 + tx * 8];
        float4 x1 = *(const float4*)&Xs[c * 64 + tx * 8 + 4];
#pragma unroll
        for (int rr = 0; rr < 6; rr++) {
            float w = Ws[c * 97 + ty * 6 + rr];
            acc[rr][0] = fmaf(w, x0.x, acc[rr][0]);
            acc[rr][1] = fmaf(w, x0.y, acc[rr][1]);
            acc[rr][2] = fmaf(w, x0.z, acc[rr][2]);
            acc[rr][3] = fmaf(w, x0.w, acc[rr][3]);
            acc[rr][4] = fmaf(w, x1.x, acc[rr][4]);
            acc[rr][5] = fmaf(w, x1.y, acc[rr][5]);
            acc[rr][6] = fmaf(w, x1.z, acc[rr][6]);
            acc[rr][7] = fmaf(w, x1.w, acc[rr][7]);
        }
    }

#pragma unroll
    for (int rr = 0; rr < 6; rr++) {
        int r = ty * 6 + rr;
        float tv = t_arr[r];
        float* dst;
        if (r < 16)      dst = g_q + ((size_t)b * CKD + r) * NPIX + n0;
        else if (r < 32) dst = g_k + ((size_t)b * CKD + (r - 16)) * NPIX + n0;
        else             dst = g_v + ((size_t)b * CD  + (r - 32)) * NPIX + n0;
        float4 o0, o1;
        o0.x = acc[rr][0] + tv; o0.y = acc[rr][1] + tv;
        o0.z = acc[rr][2] + tv; o0.w = acc[rr][3] + tv;
        o1.x = acc[rr][4] + tv; o1.y = acc[rr][5] + tv;
        o1.z = acc[rr][6] + tv; o1.w = acc[rr][7] + tv;
        *(float4*)&dst[tx * 8]     = o0;
        *(float4*)&dst[tx * 8 + 4] = o1;
    }
}

// ---------------- tensor-core flash attention, 64q x 64k tiles -------------
// 8 warps. Warp w: q-rows (w&3)*16..+15 ; key/d half (w>>2)*32..+31.
// Softmax phase keeps the audited scalar mapping: ty=tid>>4 (4 rows), tx=tid&15.
__global__ __launch_bounds__(256) void attn_kernel(
    const float* __restrict__ attn_bias, int head)
{
    __shared__ float Qs[64 * 17];   // [q][kd], tf32 bit patterns
    __shared__ float Ks[64 * 17];   // [key][kd], tf32
    __shared__ float Vt[64 * 68];   // [m][d], tf32; reused for fp32 output staging
    __shared__ float Ps[64 * 68];   // raw S (fp32) then probs (tf32)
    __shared__ float Bs[64];
    __shared__ float facS[64];
    __shared__ float linvS[64];

    int qt = blockIdx.x, b = blockIdx.y;
    int tid = threadIdx.x;
    int lane = tid & 31;
    int w = tid >> 5;
    int g = lane >> 2, c = lane & 3;
    int qw = (w & 3) * 16;
    int kh = (w >> 2) * 32;
    int ty = tid >> 4, tx = tid & 15;

    const float* qp = g_q + ((size_t)b * CKD) * NPIX + qt * 64;
    const float* kp = g_k + ((size_t)b * CKD) * NPIX;
    const float* vp = g_v + ((size_t)b * CD ) * NPIX;
    const float* bp = attn_bias + (size_t)head * NPIX;

    uint32_t* QsU = (uint32_t*)Qs;
    uint32_t* KsU = (uint32_t*)Ks;
    uint32_t* VtU = (uint32_t*)Vt;
    uint32_t* PsU = (uint32_t*)Ps;

    // Q tile once: [q][17] tf32
    for (int e = tid; e < CKD * 64; e += 256) {
        int q = e & 63, kd = e >> 6;
        QsU[q * 17 + kd] = f2tf32(qp[(size_t)kd * NPIX + q]);
    }

    float o[4][4];
#pragma unroll
    for (int n = 0; n < 4; n++)
#pragma unroll
        for (int i = 0; i < 4; i++) o[n][i] = 0.f;

    float mrun[4], lrun[4];
#pragma unroll
    for (int r = 0; r < 4; r++) { mrun[r] = -1e30f; lrun[r] = 0.f; }
    const float CLOG = 0.25f * LOG2E;

    for (int kt = 0; kt < 25; kt++) {
        __syncthreads();   // Ks/Vt safe to overwrite
        {
            const float* kpt = kp + kt * 64;
            for (int e = tid; e < CKD * 64; e += 256) {
                int key = e & 63, kd = e >> 6;
                KsU[key * 17 + kd] = f2tf32(kpt[(size_t)kd * NPIX + key]);
            }
            const float* vpt = vp + kt * 64;
            for (int e = tid; e < CD * 64; e += 256) {
                int m = e & 63, dd = e >> 6;
                VtU[m * 68 + dd] = f2tf32(vpt[(size_t)dd * NPIX + m]);
            }
            if (tid < 64) Bs[tid] = bp[kt * 64 + tid] * LOG2E;
        }
        __syncthreads();

        // ---- QK^T via mma: S[16q x 32k] per warp ----
        {
            float s[4][4];
#pragma unroll
            for (int n = 0; n < 4; n++)
#pragma unroll
                for (int i = 0; i < 4; i++) s[n][i] = 0.f;

#pragma unroll
            for (int ks = 0; ks < 16; ks += 8) {
                uint32_t a0 = QsU[(qw + g) * 17 + ks + c];
                uint32_t a1 = QsU[(qw + g + 8) * 17 + ks + c];
                uint32_t a2 = QsU[(qw + g) * 17 + ks + c + 4];
                uint32_t a3 = QsU[(qw + g + 8) * 17 + ks + c + 4];
#pragma unroll
                for (int n = 0; n < 4; n++) {
                    int kb = kh + n * 8;
                    uint32_t b0 = KsU[(kb + g) * 17 + ks + c];
                    uint32_t b1 = KsU[(kb + g) * 17 + ks + c + 4];
                    mma_tf32(s[n][0], s[n][1], s[n][2], s[n][3],
                             a0, a1, a2, a3, b0, b1);
                }
            }
#pragma unroll
            for (int n = 0; n < 4; n++) {
                int kb = kh + n * 8;
                *(float2*)&Ps[(qw + g) * 68 + kb + 2 * c]     = make_float2(s[n][0], s[n][1]);
                *(float2*)&Ps[(qw + g + 8) * 68 + kb + 2 * c] = make_float2(s[n][2], s[n][3]);
            }
        }
        __syncthreads();

        // ---- softmax (audited scalar path; reads raw S, writes tf32 probs) ----
        {
            float b0 = Bs[tx * 4], b1 = Bs[tx * 4 + 1], b2 = Bs[tx * 4 + 2], b3 = Bs[tx * 4 + 3];
#pragma unroll
            for (int r = 0; r < 4; r++) {
                float4 sv = *(const float4*)&Ps[(ty * 4 + r) * 68 + tx * 4];
                float s0 = fmaf(sv.x, CLOG, b0);
                float s1 = fmaf(sv.y, CLOG, b1);
                float s2 = fmaf(sv.z, CLOG, b2);
                float s3 = fmaf(sv.w, CLOG, b3);

                float mx = fmaxf(fmaxf(s0, s1), fmaxf(s2, s3));
                mx = fmaxf(mx, __shfl_xor_sync(0xffffffffu, mx, 1));
                mx = fmaxf(mx, __shfl_xor_sync(0xffffffffu, mx, 2));
                mx = fmaxf(mx, __shfl_xor_sync(0xffffffffu, mx, 4));
                mx = fmaxf(mx, __shfl_xor_sync(0xffffffffu, mx, 8));
                float mn  = fmaxf(mrun[r], mx);
                float fac = fexp2(mrun[r] - mn);
                mrun[r] = mn;

                float p0 = __uint_as_float(f2tf32(fexp2(s0 - mn)));
                float p1 = __uint_as_float(f2tf32(fexp2(s1 - mn)));
                float p2 = __uint_as_float(f2tf32(fexp2(s2 - mn)));
                float p3 = __uint_as_float(f2tf32(fexp2(s3 - mn)));
                float4 pq; pq.x = p0; pq.y = p1; pq.z = p2; pq.w = p3;
                *(float4*)&Ps[(ty * 4 + r) * 68 + tx * 4] = pq;

                float rs = (p0 + p1) + (p2 + p3);
                rs += __shfl_xor_sync(0xffffffffu, rs, 1);
                rs += __shfl_xor_sync(0xffffffffu, rs, 2);
                rs += __shfl_xor_sync(0xffffffffu, rs, 4);
                rs += __shfl_xor_sync(0xffffffffu, rs, 8);
                lrun[r] = lrun[r] * fac + rs;
                if (tx == 0) facS[ty * 4 + r] = fac;
            }
        }
        __syncthreads();

        // ---- rescale + P·V via mma: O[16q x 32d] per warp ----
        {
            float f1 = facS[qw + g], f2 = facS[qw + g + 8];
#pragma unroll
            for (int n = 0; n < 4; n++) {
                o[n][0] *= f1; o[n][1] *= f1;
                o[n][2] *= f2; o[n][3] *= f2;
            }
#pragma unroll
            for (int ks8 = 0; ks8 < 8; ks8++) {
                int m0 = ks8 * 8;
                uint32_t a0 = PsU[(qw + g) * 68 + m0 + c];
                uint32_t a1 = PsU[(qw + g + 8) * 68 + m0 + c];
                uint32_t a2 = PsU[(qw + g) * 68 + m0 + c + 4];
                uint32_t a3 = PsU[(qw + g + 8) * 68 + m0 + c + 4];
#pragma unroll
                for (int n = 0; n < 4; n++) {
                    int db = kh + n * 8;
                    uint32_t b0 = VtU[(m0 + c) * 68 + db + g];
                    uint32_t b1 = VtU[(m0 + c + 4) * 68 + db + g];
                    mma_tf32(o[n][0], o[n][1], o[n][2], o[n][3],
                             a0, a1, a2, a3, b0, b1);
                }
            }
        }
    }

    // final normalization factors
#pragma unroll
    for (int r = 0; r < 4; r++)
        if (tx == 0) linvS[ty * 4 + r] = 1.0f / lrun[r];
    __syncthreads();

    // stage transpose [d][q] into Vt (fp32)
    {
        float i1 = linvS[qw + g], i2 = linvS[qw + g + 8];
#pragma unroll
        for (int n = 0; n < 4; n++) {
            int db = kh + n * 8;
            Vt[(db + 2 * c) * 68 + qw + g]         = o[n][0] * i1;
            Vt[(db + 2 * c + 1) * 68 + qw + g]     = o[n][1] * i1;
            Vt[(db + 2 * c) * 68 + qw + g + 8]     = o[n][2] * i2;
            Vt[(db + 2 * c + 1) * 68 + qw + g + 8] = o[n][3] * i2;
        }
    }
    __syncthreads();
    float* op = g_o + ((size_t)b * CDIM + head * CD) * NPIX + qt * 64;
    for (int e = tid; e < CD * 64; e += 256) {
        int dd = e >> 6, r = e & 63;
        op[(size_t)dd * NPIX + r] = Vt[dd * 68 + r];
    }
}

// ---------------- final 256x256 projection + BN + ReLU ---------------------
__global__ __launch_bounds__(128) void proj_kernel(
    const float* __restrict__ proj_w, const float* __restrict__ pg,
    const float* __restrict__ pb, const float* __restrict__ pm,
    const float* __restrict__ pv, float* __restrict__ out)
{
    __shared__ float Ws[64 * 65];
    __shared__ float Xs[64 * 64];

    int nt = blockIdx.x, ot = blockIdx.y, b = blockIdx.z;
    int tid = threadIdx.x;
    int ty = tid >> 4, tx = tid & 15;
    int n0 = nt * 64, o0 = ot * 64;

    float acc[8][4];
#pragma unroll
    for (int r = 0; r < 8; r++)
#pragma unroll
        for (int c = 0; c < 4; c++) acc[r][c] = 0.f;

    for (int ck = 0; ck < 4; ck++) {
        __syncthreads();
        for (int e = tid; e < 4096; e += 128) {
            int c = e & 63, o = e >> 6;
            Ws[c * 65 + o] = proj_w[(size_t)(o0 + o) * CDIM + ck * 64 + c];
        }
        for (int e = tid; e < 4096; e += 128) {
            int n = e & 63, c = e >> 6;
            Xs[c * 64 + n] = g_o[((size_t)b * CDIM + ck * 64 + c) * NPIX + n0 + n];
        }
        __syncthreads();
#pragma unroll 4
        for (int c = 0; c < 64; c++) {
            float4 xv = *(const float4*)&Xs[c * 64 + tx * 4];
#pragma unroll
            for (int r = 0; r < 8; r++) {
                float wv = Ws[c * 65 + ty * 8 + r];
                acc[r][0] = fmaf(wv, xv.x, acc[r][0]);
                acc[r][1] = fmaf(wv, xv.y, acc[r][1]);
                acc[r][2] = fmaf(wv, xv.z, acc[r][2]);
                acc[r][3] = fmaf(wv, xv.w, acc[r][3]);
            }
        }
    }

#pragma unroll
    for (int r = 0; r < 8; r++) {
        int o = o0 + ty * 8 + r;
        float sc = pg[o] * rsqrtf(pv[o] + EPSB);
        float tv = pb[o] - pm[o] * sc;
        float4 res;
        res.x = fmaxf(fmaf(acc[r][0], sc, tv), 0.f);
        res.y = fmaxf(fmaf(acc[r][1], sc, tv), 0.f);
        res.z = fmaxf(fmaf(acc[r][2], sc, tv), 0.f);
        res.w = fmaxf(fmaf(acc[r][3], sc, tv), 0.f);
        *(float4*)&out[((size_t)b * CDIM + o) * NPIX + n0 + tx * 4] = res;
    }
}

// ---------------------------------------------------------------------------
extern "C" void kernel_launch(void* const* d_in, const int* in_sizes, int n_in,
                              void* d_out, int out_size)
{
    (void)in_sizes; (void)n_in; (void)out_size;
    const float* x      = (const float*)d_in[0];
    const float* dw_w   = (const float*)d_in[1];
    const float* dw_g   = (const float*)d_in[2];
    const float* dw_b   = (const float*)d_in[3];
    const float* dw_m   = (const float*)d_in[4];
    const float* dw_v   = (const float*)d_in[5];
    const float* q_w    = (const float*)d_in[6];
    const float* q_g    = (const float*)d_in[7];
    const float* q_b    = (const float*)d_in[8];
    const float* q_m    = (const float*)d_in[9];
    const float* q_v    = (const float*)d_in[10];
    const float* k_w    = (const float*)d_in[11];
    const float* k_g    = (const float*)d_in[12];
    const float* k_b    = (const float*)d_in[13];
    const float* k_m    = (const float*)d_in[14];
    const float* k_v    = (const float*)d_in[15];
    const float* v_w    = (const float*)d_in[16];
    const float* v_g    = (const float*)d_in[17];
    const float* v_b    = (const float*)d_in[18];
    const float* v_m    = (const float*)d_in[19];
    const float* v_v    = (const float*)d_in[20];
    const float* proj_w = (const float*)d_in[21];
    const float* proj_g = (const float*)d_in[22];
    const float* proj_b = (const float*)d_in[23];
    const float* proj_m = (const float*)d_in[24];
    const float* proj_v = (const float*)d_in[25];
    const float* abias  = (const float*)d_in[26];
    float* out = (float*)d_out;

    for (int h = 0; h < NHEADS; h++) {
        dwconv_kernel<<<dim3(CHD, NB), 256>>>(x, dw_w, dw_g, dw_b, dw_m, dw_v, h);
        qkv_kernel<<<dim3(25, NB), 128>>>(q_w, q_g, q_b, q_m, q_v,
                                          k_w, k_g, k_b, k_m, k_v,
                                          v_w, v_g, v_b, v_m, v_v, h);
        attn_kernel<<<dim3(25, NB), 256>>>(abias, h);
    }
    proj_kernel<<<dim3(25, 4, NB), 128>>>(proj_w, proj_g, proj_b, proj_m, proj_v, out);
}